// round 10
// baseline (speedup 1.0000x reference)
#include <cuda_runtime.h>
#include <cuda_fp16.h>
#include <cstdint>

#define BATCH 4096
#define INF   1024
#define OUTF  1024
#define NL    16

#define BM 128
#define BN 128
#define BK 128                 // 8 i-values x 16 leaves per chunk
#define NIT (INF/8)            // 128 pw chunks
#define KCAT (INF*NL)

// smem layout (bytes)
#define X_OFF    0
#define X_BUF_B  2048          // 128 rows x 8 i x fp16
#define B_OFF    (3*X_BUF_B)   // 6144
#define B_PITCH  272           // 256B row + 16B pad (LDSM conflict-free)
#define B_BUF_B  (BN*B_PITCH)  // 34816
#define SMEM_TOTAL (B_OFF + 3*B_BUF_B)   // 110592 bytes -> 2 CTA/SM

#define NPW_BLOCKS ((size_t)OUTF*KCAT/8/256)   // 8192
#define NX_BLOCKS  ((size_t)BATCH*INF/8/256)   // 2048

// device scratch (allocation-free)
__device__ __half g_gh[BATCH * NL];            // gating in fp16
__device__ __half g_xh[(size_t)BATCH * INF];   // x in fp16 (row-major)
__device__ __half g_pwh[(size_t)OUTF * KCAT];  // pw in fp16
__device__ __half g_pbh[OUTF * NL];            // pb in fp16

__device__ __forceinline__ uint32_t smem_u32_of(const void* p) {
    uint32_t a;
    asm("{ .reg .u64 t; cvta.to.shared.u64 t, %1; cvt.u32.u64 %0, t; }" : "=r"(a) : "l"(p));
    return a;
}
__device__ __forceinline__ uint32_t h2u(float lo, float hi) {
    __half2 h = __floats2half2_rn(lo, hi);
    return *(uint32_t*)&h;
}
__device__ __forceinline__ uint32_t hu(__half2 h) { return *(uint32_t*)&h; }
__device__ __forceinline__ void cp_async16(uint32_t sa, const void* ga) {
    asm volatile("cp.async.cg.shared.global [%0], [%1], 16;" :: "r"(sa), "l"(ga));
}
__device__ __forceinline__ void mma_f16(float* c, uint32_t a0, uint32_t a1,
                                        uint32_t a2, uint32_t a3,
                                        uint32_t b0, uint32_t b1) {
    asm volatile(
        "mma.sync.aligned.m16n8k16.row.col.f32.f16.f16.f32 "
        "{%0,%1,%2,%3}, {%4,%5,%6,%7}, {%8,%9}, {%0,%1,%2,%3};"
        : "+f"(c[0]), "+f"(c[1]), "+f"(c[2]), "+f"(c[3])
        : "r"(a0), "r"(a1), "r"(a2), "r"(a3), "r"(b0), "r"(b1));
}
__device__ __forceinline__ void ldsm_x4(uint32_t& r0, uint32_t& r1, uint32_t& r2, uint32_t& r3,
                                        uint32_t addr) {
    asm volatile("ldmatrix.sync.aligned.m8n8.x4.shared.b16 {%0,%1,%2,%3}, [%4];"
                 : "=r"(r0), "=r"(r1), "=r"(r2), "=r"(r3) : "r"(addr));
}

// ---------------------------------------------------------------------------
// prep: pw, x, pb -> fp16 (single launch, three grid sections)
// ---------------------------------------------------------------------------
__global__ __launch_bounds__(256)
void conv_kernel(const float* __restrict__ pw, const float* __restrict__ x,
                 const float* __restrict__ pb) {
    size_t bid = blockIdx.x;
    const float* src;
    __half* dst;
    size_t idx;
    if (bid < NPW_BLOCKS)            { src = pw; dst = g_pwh; idx = bid * 256 + threadIdx.x; }
    else if (bid < NPW_BLOCKS + NX_BLOCKS)
                                     { src = x;  dst = g_xh;  idx = (bid - NPW_BLOCKS) * 256 + threadIdx.x; }
    else                             { src = pb; dst = g_pbh; idx = (bid - NPW_BLOCKS - NX_BLOCKS) * 256 + threadIdx.x; }
    float4 v0 = ((const float4*)src)[idx * 2];
    float4 v1 = ((const float4*)src)[idx * 2 + 1];
    uint4 o;
    o.x = h2u(v0.x, v0.y); o.y = h2u(v0.z, v0.w);
    o.z = h2u(v1.x, v1.y); o.w = h2u(v1.z, v1.w);
    ((uint4*)dst)[idx] = o;
}

// ---------------------------------------------------------------------------
// gating: g = softmax(x @ gw + gb) -> fp16. 256 blocks, 2 rows/warp,
// float4 x loads, float4 gw reads (pitch 20).
// ---------------------------------------------------------------------------
__global__ __launch_bounds__(256)
void gating_kernel(const float* __restrict__ x,
                   const float* __restrict__ gw,
                   const float* __restrict__ gb) {
    extern __shared__ float gw_s[];   // [1024][20]
    int tid = threadIdx.x, warp = tid >> 5, lane = tid & 31;

    for (int idx = tid; idx < INF * NL; idx += 256) {
        int i = idx >> 4, l = idx & 15;
        gw_s[i * 20 + l] = gw[idx];
    }
    __syncthreads();

    #pragma unroll 1
    for (int r = 0; r < 2; r++) {
        int row = blockIdx.x * 16 + warp * 2 + r;
        const float4* xr = (const float4*)(x + (size_t)row * INF);

        float acc[16];
        #pragma unroll
        for (int l = 0; l < 16; l++) acc[l] = 0.f;

        #pragma unroll 2
        for (int jj = 0; jj < 8; jj++) {
            int i0 = jj * 128 + lane * 4;
            float4 xv = xr[jj * 32 + lane];
            float xs[4] = {xv.x, xv.y, xv.z, xv.w};
            #pragma unroll
            for (int d = 0; d < 4; d++) {
                const float4* gr = (const float4*)(gw_s + (i0 + d) * 20);
                #pragma unroll
                for (int c4 = 0; c4 < 4; c4++) {
                    float4 gv = gr[c4];
                    acc[c4 * 4 + 0] = fmaf(xs[d], gv.x, acc[c4 * 4 + 0]);
                    acc[c4 * 4 + 1] = fmaf(xs[d], gv.y, acc[c4 * 4 + 1]);
                    acc[c4 * 4 + 2] = fmaf(xs[d], gv.z, acc[c4 * 4 + 2]);
                    acc[c4 * 4 + 3] = fmaf(xs[d], gv.w, acc[c4 * 4 + 3]);
                }
            }
        }
        #pragma unroll
        for (int o = 16; o > 0; o >>= 1)
            #pragma unroll
            for (int l = 0; l < 16; l++)
                acc[l] += __shfl_xor_sync(0xffffffffu, acc[l], o);

        if (lane < 16) {
            float v[16], m = -1e30f;
            #pragma unroll
            for (int l = 0; l < 16; l++) { v[l] = acc[l] + gb[l]; m = fmaxf(m, v[l]); }
            float s = 0.f;
            #pragma unroll
            for (int l = 0; l < 16; l++) { v[l] = __expf(v[l] - m); s += v[l]; }
            g_gh[row * NL + lane] = __float2half(v[lane] / s);
        }
    }
}

// ---------------------------------------------------------------------------
// main GEMM: out = Y @ PW^T + g @ pb^T, mma.sync fp16 m16n8k16, fp32 accum.
// A fragments generated in registers; BK=128 chunks (halved barrier count),
// compute processes each chunk in two 64-k halves to cap register use.
// ---------------------------------------------------------------------------
__global__ __launch_bounds__(256, 2)
void moe_mma_kernel(float* __restrict__ out) {
    extern __shared__ char smc[];

    const int tid  = threadIdx.x;
    const int warp = tid >> 5, lane = tid & 31;
    const int m_blk = blockIdx.y * BM;
    const int n_blk = blockIdx.x * BN;
    const int warpM = warp & 1, warpN = warp >> 1;   // 2 x 4 warp grid, 64x32 each

    const int q = lane >> 2, cc = lane & 3;
    const int f16c = tid & 15, rb = tid >> 4;       // B loader roles

    // ---- g fragment pairs in registers (k-invariant) ----
    __half2 tg[4][4];
    #pragma unroll
    for (int mt = 0; mt < 4; mt++) {
        int r0 = m_blk + warpM * 64 + mt * 16 + q;
        int r1 = r0 + 8;
        tg[mt][0] = *(const __half2*)(g_gh + r0 * NL + 2 * cc);
        tg[mt][1] = *(const __half2*)(g_gh + r1 * NL + 2 * cc);
        tg[mt][2] = *(const __half2*)(g_gh + r0 * NL + 2 * cc + 8);
        tg[mt][3] = *(const __half2*)(g_gh + r1 * NL + 2 * cc + 8);
    }

    auto loadX = [&](int c, int buf) {
        if (tid < 128)
            cp_async16(smem_u32_of(smc + X_OFF + buf * X_BUF_B) + (uint32_t)tid * 16,
                       g_xh + (size_t)(m_blk + tid) * INF + c * 8);
    };
    auto loadB = [&](int c, int buf) {
        const __half* src = g_pwh + (size_t)n_blk * KCAT + (size_t)c * BK;
        uint32_t dst = smem_u32_of(smc + B_OFF + buf * B_BUF_B);
        #pragma unroll
        for (int qq = 0; qq < 8; qq++) {
            int row = rb + qq * 16;
            cp_async16(dst + (uint32_t)(row * B_PITCH + f16c * 16),
                       src + (size_t)row * KCAT + f16c * 8);
        }
    };
    auto loadB_bias = [&](int buf) {
        int f2 = tid & 1, row = tid >> 1;     // 128 rows x 32B
        uint32_t dst = smem_u32_of(smc + B_OFF + buf * B_BUF_B);
        cp_async16(dst + (uint32_t)(row * B_PITCH + f2 * 16),
                   g_pbh + (size_t)(n_blk + row) * NL + f2 * 8);
    };

    float acc[4][4][4];
    #pragma unroll
    for (int mt = 0; mt < 4; mt++)
        #pragma unroll
        for (int nt = 0; nt < 4; nt++)
            #pragma unroll
            for (int j = 0; j < 4; j++) acc[mt][nt][j] = 0.f;

    // B ldmatrix per-thread base (R6-proven mapping)
    const int lrow = warpN * 32 + (lane & 7) + ((lane >> 4) << 3);
    const uint32_t lcol16 = ((lane >> 3) & 1) << 4;
    const uint32_t bB0 = smem_u32_of(smc + B_OFF) + (uint32_t)lrow * B_PITCH + lcol16;

    auto compute = [&](int buf) {
        const char* xt = smc + X_OFF + buf * X_BUF_B + (warpM * 64) * 16;
        const uint32_t bb = bB0 + (uint32_t)buf * B_BUF_B;
        #pragma unroll
        for (int h = 0; h < 2; h++) {
            // x fragments for this 64-k half: 2 half2 per row (i pairs)
            __half2 xp0[4], xp1[4], xq0[4], xq1[4];
            #pragma unroll
            for (int mt = 0; mt < 4; mt++) {
                const __half2* p  = (const __half2*)(xt + (mt * 16 + q) * 16 + h * 8);
                const __half2* pq = (const __half2*)(xt + (mt * 16 + q + 8) * 16 + h * 8);
                xp0[mt] = p[0];  xp1[mt] = p[1];
                xq0[mt] = pq[0]; xq1[mt] = pq[1];
            }
            #pragma unroll
            for (int ks = 0; ks < 4; ks++) {
                uint32_t b[4][2];
                ldsm_x4(b[0][0], b[0][1], b[1][0], b[1][1], bb + (h * 4 + ks) * 32);
                ldsm_x4(b[2][0], b[2][1], b[3][0], b[3][1], bb + 16 * B_PITCH + (h * 4 + ks) * 32);
                #pragma unroll
                for (int mt = 0; mt < 4; mt++) {
                    __half2 xs0 = (ks == 0) ? __low2half2(xp0[mt]) :
                                  (ks == 1) ? __high2half2(xp0[mt]) :
                                  (ks == 2) ? __low2half2(xp1[mt]) : __high2half2(xp1[mt]);
                    __half2 xs1 = (ks == 0) ? __low2half2(xq0[mt]) :
                                  (ks == 1) ? __high2half2(xq0[mt]) :
                                  (ks == 2) ? __low2half2(xq1[mt]) : __high2half2(xq1[mt]);
                    uint32_t a0 = hu(__hmul2(xs0, tg[mt][0]));
                    uint32_t a1 = hu(__hmul2(xs1, tg[mt][1]));
                    uint32_t a2 = hu(__hmul2(xs0, tg[mt][2]));
                    uint32_t a3 = hu(__hmul2(xs1, tg[mt][3]));
                    #pragma unroll
                    for (int nt = 0; nt < 4; nt++)
                        mma_f16(acc[mt][nt], a0, a1, a2, a3, b[nt][0], b[nt][1]);
                }
            }
        }
    };
    auto compute_bias = [&](int buf) {
        const uint32_t bb = bB0 + (uint32_t)buf * B_BUF_B;
        uint32_t b[4][2];
        ldsm_x4(b[0][0], b[0][1], b[1][0], b[1][1], bb);
        ldsm_x4(b[2][0], b[2][1], b[3][0], b[3][1], bb + 16 * B_PITCH);
        #pragma unroll
        for (int mt = 0; mt < 4; mt++) {
            uint32_t a0 = hu(tg[mt][0]), a1 = hu(tg[mt][1]);
            uint32_t a2 = hu(tg[mt][2]), a3 = hu(tg[mt][3]);
            #pragma unroll
            for (int nt = 0; nt < 4; nt++)
                mma_f16(acc[mt][nt], a0, a1, a2, a3, b[nt][0], b[nt][1]);
        }
    };

    // ---- prologue: chunk 0 in flight ----
    loadX(0, 0);
    loadB(0, 0);
    asm volatile("cp.async.commit_group;" ::: "memory");

    // ---- main loop: distance-1, one barrier per 128-k chunk ----
    #pragma unroll 1
    for (int it = 0; it <= NIT; it++) {
        const int nc = it + 1;
        if (nc < NIT)        { loadX(nc, nc % 3); loadB(nc, nc % 3); }
        else if (nc == NIT)  { loadB_bias(nc % 3); }
        asm volatile("cp.async.commit_group;" ::: "memory");
        if (nc <= NIT) asm volatile("cp.async.wait_group 1;" ::: "memory");
        else           asm volatile("cp.async.wait_group 0;" ::: "memory");
        __syncthreads();
        if (it < NIT) compute(it % 3);
        else          compute_bias(it % 3);
    }

    // ---- epilogue: fragment store, 8B quad-coalesced ----
    #pragma unroll
    for (int mt = 0; mt < 4; mt++) {
        int m0 = m_blk + warpM * 64 + mt * 16 + (lane >> 2);
        #pragma unroll
        for (int nt = 0; nt < 4; nt++) {
            int n = n_blk + warpN * 32 + nt * 8 + 2 * (lane & 3);
            *(float2*)(out + (size_t)m0 * OUTF + n)       = make_float2(acc[mt][nt][0], acc[mt][nt][1]);
            *(float2*)(out + (size_t)(m0 + 8) * OUTF + n) = make_float2(acc[mt][nt][2], acc[mt][nt][3]);
        }
    }
}

// ---------------------------------------------------------------------------
extern "C" void kernel_launch(void* const* d_in, const int* in_sizes, int n_in,
                              void* d_out, int out_size) {
    const float* x  = (const float*)d_in[0];
    const float* gw = (const float*)d_in[1];
    const float* gb = (const float*)d_in[2];
    const float* pw = (const float*)d_in[3];
    const float* pb = (const float*)d_in[4];
    float* out = (float*)d_out;

    cudaFuncSetAttribute(gating_kernel, cudaFuncAttributeMaxDynamicSharedMemorySize,
                         INF * 20 * 4);
    cudaFuncSetAttribute(moe_mma_kernel, cudaFuncAttributeMaxDynamicSharedMemorySize,
                         SMEM_TOTAL);

    gating_kernel<<<BATCH / 16, 256, INF * 20 * 4>>>(x, gw, gb);
    conv_kernel<<<(unsigned)(NPW_BLOCKS + NX_BLOCKS + (OUTF * NL) / 8 / 256), 256>>>(pw, x, pb);

    dim3 grid(OUTF / BN, BATCH / BM);   // (8, 32) = 256 CTAs, 2/SM, one wave
    moe_mma_kernel<<<grid, 256, SMEM_TOTAL>>>(out);
}

// round 11
// speedup vs baseline: 1.0187x; 1.0187x over previous
#include <cuda_runtime.h>
#include <cuda_fp16.h>
#include <cstdint>

#define BATCH 4096
#define INF   1024
#define OUTF  1024
#define NL    16

#define BM 128
#define BN 128
#define BK 64                  // 4 i-values x 16 leaves per chunk
#define NIT (INF/4)            // 256 pw chunks
#define KCAT (INF*NL)

// smem layout (bytes)
#define X_OFF    0
#define X_BUF_B  1024          // 128 rows x 4 i x fp16
#define B_OFF    (3*X_BUF_B)   // 3072 (128B-aligned)
#define B_BUF_B  (BN*144)      // 18432 (144B pitch, LDSM conflict-free)
#define SMEM_TOTAL (B_OFF + 3*B_BUF_B)   // 58368 bytes

#define NPW_BLOCKS ((size_t)OUTF*KCAT/8/256)   // 8192
#define NX_BLOCKS  ((size_t)BATCH*INF/8/256)   // 2048

// device scratch (allocation-free)
__device__ __half g_gh[BATCH * NL];            // gating in fp16
__device__ __half g_xh[(size_t)BATCH * INF];   // x in fp16 (row-major)
__device__ __half g_pwh[(size_t)OUTF * KCAT];  // pw in fp16
__device__ __half g_pbh[OUTF * NL];            // pb in fp16

__device__ __forceinline__ uint32_t smem_u32_of(const void* p) {
    uint32_t a;
    asm("{ .reg .u64 t; cvta.to.shared.u64 t, %1; cvt.u32.u64 %0, t; }" : "=r"(a) : "l"(p));
    return a;
}
__device__ __forceinline__ uint32_t h2u(float lo, float hi) {
    __half2 h = __floats2half2_rn(lo, hi);
    return *(uint32_t*)&h;
}
__device__ __forceinline__ uint32_t hu(__half2 h) { return *(uint32_t*)&h; }
__device__ __forceinline__ void cp_async16(uint32_t sa, const void* ga) {
    asm volatile("cp.async.cg.shared.global [%0], [%1], 16;" :: "r"(sa), "l"(ga));
}
__device__ __forceinline__ void cp_async8(uint32_t sa, const void* ga) {
    asm volatile("cp.async.ca.shared.global [%0], [%1], 8;" :: "r"(sa), "l"(ga));
}
__device__ __forceinline__ void mma_f16(float* c, uint32_t a0, uint32_t a1,
                                        uint32_t a2, uint32_t a3,
                                        uint32_t b0, uint32_t b1) {
    asm volatile(
        "mma.sync.aligned.m16n8k16.row.col.f32.f16.f16.f32 "
        "{%0,%1,%2,%3}, {%4,%5,%6,%7}, {%8,%9}, {%0,%1,%2,%3};"
        : "+f"(c[0]), "+f"(c[1]), "+f"(c[2]), "+f"(c[3])
        : "r"(a0), "r"(a1), "r"(a2), "r"(a3), "r"(b0), "r"(b1));
}
__device__ __forceinline__ void ldsm_x4(uint32_t& r0, uint32_t& r1, uint32_t& r2, uint32_t& r3,
                                        uint32_t addr) {
    asm volatile("ldmatrix.sync.aligned.m8n8.x4.shared.b16 {%0,%1,%2,%3}, [%4];"
                 : "=r"(r0), "=r"(r1), "=r"(r2), "=r"(r3) : "r"(addr));
}

// ---------------------------------------------------------------------------
// prep: pw, x, pb -> fp16 (single launch, three grid sections)
// ---------------------------------------------------------------------------
__global__ __launch_bounds__(256)
void conv_kernel(const float* __restrict__ pw, const float* __restrict__ x,
                 const float* __restrict__ pb) {
    size_t bid = blockIdx.x;
    const float* src;
    __half* dst;
    size_t idx;
    if (bid < NPW_BLOCKS)            { src = pw; dst = g_pwh; idx = bid * 256 + threadIdx.x; }
    else if (bid < NPW_BLOCKS + NX_BLOCKS)
                                     { src = x;  dst = g_xh;  idx = (bid - NPW_BLOCKS) * 256 + threadIdx.x; }
    else                             { src = pb; dst = g_pbh; idx = (bid - NPW_BLOCKS - NX_BLOCKS) * 256 + threadIdx.x; }
    float4 v0 = ((const float4*)src)[idx * 2];
    float4 v1 = ((const float4*)src)[idx * 2 + 1];
    uint4 o;
    o.x = h2u(v0.x, v0.y); o.y = h2u(v0.z, v0.w);
    o.z = h2u(v1.x, v1.y); o.w = h2u(v1.z, v1.w);
    ((uint4*)dst)[idx] = o;
}

// ---------------------------------------------------------------------------
// gating: g = softmax(x @ gw + gb) -> fp16.
// 256 blocks, 2 rows/warp. gw filled via float4 LDG into pitch-17 smem
// (conflict-free scalar reads). x row preloaded into 32 regs (high MLP).
// ---------------------------------------------------------------------------
__global__ __launch_bounds__(256)
void gating_kernel(const float* __restrict__ x,
                   const float* __restrict__ gw,
                   const float* __restrict__ gb) {
    extern __shared__ float gw_s[];   // [1024][17]
    int tid = threadIdx.x, warp = tid >> 5, lane = tid & 31;

    // vectorized fill: 16 float4 per thread
    #pragma unroll
    for (int it = 0; it < 16; it++) {
        int idx = tid + it * 256;                 // 0..4095 float4s
        float4 v = ((const float4*)gw)[idx];
        int i = idx >> 2, l4 = (idx & 3) * 4;
        float* d = gw_s + i * 17 + l4;
        d[0] = v.x; d[1] = v.y; d[2] = v.z; d[3] = v.w;
    }
    __syncthreads();

    #pragma unroll 1
    for (int r = 0; r < 2; r++) {
        int row = blockIdx.x * 16 + warp * 2 + r;
        const float* xr = x + (size_t)row * INF;

        // preload full x stripe (32 values) — batched LDGs
        float xv[32];
        #pragma unroll
        for (int jj = 0; jj < 32; jj++) xv[jj] = xr[lane + 32 * jj];

        float acc[16];
        #pragma unroll
        for (int l = 0; l < 16; l++) acc[l] = 0.f;

        #pragma unroll
        for (int jj = 0; jj < 32; jj++) {
            const float* gr = gw_s + (lane + 32 * jj) * 17;
            #pragma unroll
            for (int l = 0; l < 16; l++) acc[l] = fmaf(xv[jj], gr[l], acc[l]);
        }
        #pragma unroll
        for (int o = 16; o > 0; o >>= 1)
            #pragma unroll
            for (int l = 0; l < 16; l++)
                acc[l] += __shfl_xor_sync(0xffffffffu, acc[l], o);

        if (lane < 16) {
            float v[16], m = -1e30f;
            #pragma unroll
            for (int l = 0; l < 16; l++) { v[l] = acc[l] + gb[l]; m = fmaxf(m, v[l]); }
            float s = 0.f;
            #pragma unroll
            for (int l = 0; l < 16; l++) { v[l] = __expf(v[l] - m); s += v[l]; }
            g_gh[row * NL + lane] = __float2half(v[lane] / s);
        }
    }
}

// ---------------------------------------------------------------------------
// main GEMM (R8-proven config): out = Y @ PW^T + g @ pb^T, mma.sync fp16
// m16n8k16, fp32 accum. A fragments generated in registers (g in regs,
// x via 1KB smem tile). B via cp.async + ldmatrix.x4, 3-buf distance-1.
// ---------------------------------------------------------------------------
__global__ __launch_bounds__(256, 2)
void moe_mma_kernel(float* __restrict__ out) {
    extern __shared__ char smc[];

    const int tid  = threadIdx.x;
    const int warp = tid >> 5, lane = tid & 31;
    const int m_blk = blockIdx.y * BM;
    const int n_blk = blockIdx.x * BN;
    const int warpM = warp & 1, warpN = warp >> 1;   // 2 x 4 warp grid, 64x32 each

    const int q = lane >> 2, cc = lane & 3;
    const int f8 = tid & 7, rb = tid >> 3;          // B loader roles

    // ---- g fragment pairs in registers (k-invariant) ----
    __half2 tg[4][4];
    #pragma unroll
    for (int mt = 0; mt < 4; mt++) {
        int r0 = m_blk + warpM * 64 + mt * 16 + q;
        int r1 = r0 + 8;
        tg[mt][0] = *(const __half2*)(g_gh + r0 * NL + 2 * cc);
        tg[mt][1] = *(const __half2*)(g_gh + r1 * NL + 2 * cc);
        tg[mt][2] = *(const __half2*)(g_gh + r0 * NL + 2 * cc + 8);
        tg[mt][3] = *(const __half2*)(g_gh + r1 * NL + 2 * cc + 8);
    }

    auto loadX = [&](int c, int buf) {
        if (tid < 128)
            cp_async8(smem_u32_of(smc + X_OFF + buf * X_BUF_B) + (uint32_t)tid * 8,
                      g_xh + (size_t)(m_blk + tid) * INF + c * 4);
    };
    auto loadB = [&](int c, int buf) {
        const __half* src = g_pwh + (size_t)n_blk * KCAT + (size_t)c * BK;
        uint32_t dst = smem_u32_of(smc + B_OFF + buf * B_BUF_B);
        #pragma unroll
        for (int qq = 0; qq < 4; qq++) {
            int row = rb + qq * 32;
            cp_async16(dst + (uint32_t)(row * 144 + f8 * 16),
                       src + (size_t)row * KCAT + f8 * 8);
        }
    };
    auto loadB_bias = [&](int buf) {
        int f2 = tid & 1, row = tid >> 1;     // 128 rows x 32B
        uint32_t dst = smem_u32_of(smc + B_OFF + buf * B_BUF_B);
        cp_async16(dst + (uint32_t)(row * 144 + f2 * 16),
                   g_pbh + (size_t)(n_blk + row) * NL + f2 * 8);
    };

    float acc[4][4][4];
    #pragma unroll
    for (int mt = 0; mt < 4; mt++)
        #pragma unroll
        for (int nt = 0; nt < 4; nt++)
            #pragma unroll
            for (int j = 0; j < 4; j++) acc[mt][nt][j] = 0.f;

    // B ldmatrix per-thread base (R6-proven mapping)
    const int lrow = warpN * 32 + (lane & 7) + ((lane >> 4) << 3);
    const uint32_t lcol16 = ((lane >> 3) & 1) << 4;
    const uint32_t bB0 = smem_u32_of(smc + B_OFF) + (uint32_t)lrow * 144 + lcol16;

    auto compute = [&](int buf) {
        const char* xt = smc + X_OFF + buf * X_BUF_B + (warpM * 64) * 8;
        __half2 xp0[4], xp1[4], xq0[4], xq1[4];
        #pragma unroll
        for (int mt = 0; mt < 4; mt++) {
            const __half2* p  = (const __half2*)(xt + (mt * 16 + q) * 8);
            const __half2* pq = (const __half2*)(xt + (mt * 16 + q + 8) * 8);
            xp0[mt] = p[0];  xp1[mt] = p[1];
            xq0[mt] = pq[0]; xq1[mt] = pq[1];
        }
        const uint32_t bb = bB0 + (uint32_t)buf * B_BUF_B;
        #pragma unroll
        for (int ks = 0; ks < 4; ks++) {
            uint32_t b[4][2];
            ldsm_x4(b[0][0], b[0][1], b[1][0], b[1][1], bb + ks * 32);
            ldsm_x4(b[2][0], b[2][1], b[3][0], b[3][1], bb + 16 * 144 + ks * 32);
            #pragma unroll
            for (int mt = 0; mt < 4; mt++) {
                __half2 xs0 = (ks == 0) ? __low2half2(xp0[mt]) :
                              (ks == 1) ? __high2half2(xp0[mt]) :
                              (ks == 2) ? __low2half2(xp1[mt]) : __high2half2(xp1[mt]);
                __half2 xs1 = (ks == 0) ? __low2half2(xq0[mt]) :
                              (ks == 1) ? __high2half2(xq0[mt]) :
                              (ks == 2) ? __low2half2(xq1[mt]) : __high2half2(xq1[mt]);
                uint32_t a0 = hu(__hmul2(xs0, tg[mt][0]));
                uint32_t a1 = hu(__hmul2(xs1, tg[mt][1]));
                uint32_t a2 = hu(__hmul2(xs0, tg[mt][2]));
                uint32_t a3 = hu(__hmul2(xs1, tg[mt][3]));
                #pragma unroll
                for (int nt = 0; nt < 4; nt++)
                    mma_f16(acc[mt][nt], a0, a1, a2, a3, b[nt][0], b[nt][1]);
            }
        }
    };
    auto compute_bias = [&](int buf) {
        const uint32_t bb = bB0 + (uint32_t)buf * B_BUF_B;
        uint32_t b[4][2];
        ldsm_x4(b[0][0], b[0][1], b[1][0], b[1][1], bb);
        ldsm_x4(b[2][0], b[2][1], b[3][0], b[3][1], bb + 16 * 144);
        #pragma unroll
        for (int mt = 0; mt < 4; mt++) {
            uint32_t a0 = hu(tg[mt][0]), a1 = hu(tg[mt][1]);
            uint32_t a2 = hu(tg[mt][2]), a3 = hu(tg[mt][3]);
            #pragma unroll
            for (int nt = 0; nt < 4; nt++)
                mma_f16(acc[mt][nt], a0, a1, a2, a3, b[nt][0], b[nt][1]);
        }
    };

    // ---- prologue: chunk 0 in flight ----
    loadX(0, 0);
    loadB(0, 0);
    asm volatile("cp.async.commit_group;" ::: "memory");

    // ---- main loop: distance-1, one barrier per chunk ----
    #pragma unroll 1
    for (int it = 0; it <= NIT; it++) {
        const int nc = it + 1;
        if (nc < NIT)        { loadX(nc, nc % 3); loadB(nc, nc % 3); }
        else if (nc == NIT)  { loadB_bias(nc % 3); }
        asm volatile("cp.async.commit_group;" ::: "memory");
        if (nc <= NIT) asm volatile("cp.async.wait_group 1;" ::: "memory");
        else           asm volatile("cp.async.wait_group 0;" ::: "memory");
        __syncthreads();
        if (it < NIT) compute(it % 3);
        else          compute_bias(it % 3);
    }

    // ---- epilogue: fragment store, 8B quad-coalesced ----
    #pragma unroll
    for (int mt = 0; mt < 4; mt++) {
        int m0 = m_blk + warpM * 64 + mt * 16 + (lane >> 2);
        #pragma unroll
        for (int nt = 0; nt < 4; nt++) {
            int n = n_blk + warpN * 32 + nt * 8 + 2 * (lane & 3);
            *(float2*)(out + (size_t)m0 * OUTF + n)       = make_float2(acc[mt][nt][0], acc[mt][nt][1]);
            *(float2*)(out + (size_t)(m0 + 8) * OUTF + n) = make_float2(acc[mt][nt][2], acc[mt][nt][3]);
        }
    }
}

// ---------------------------------------------------------------------------
extern "C" void kernel_launch(void* const* d_in, const int* in_sizes, int n_in,
                              void* d_out, int out_size) {
    const float* x  = (const float*)d_in[0];
    const float* gw = (const float*)d_in[1];
    const float* gb = (const float*)d_in[2];
    const float* pw = (const float*)d_in[3];
    const float* pb = (const float*)d_in[4];
    float* out = (float*)d_out;

    cudaFuncSetAttribute(gating_kernel, cudaFuncAttributeMaxDynamicSharedMemorySize,
                         INF * 17 * 4);
    cudaFuncSetAttribute(moe_mma_kernel, cudaFuncAttributeMaxDynamicSharedMemorySize,
                         SMEM_TOTAL);

    gating_kernel<<<BATCH / 16, 256, INF * 17 * 4>>>(x, gw, gb);
    conv_kernel<<<(unsigned)(NPW_BLOCKS + NX_BLOCKS + (OUTF * NL) / 8 / 256), 256>>>(pw, x, pb);

    dim3 grid(OUTF / BN, BATCH / BM);   // (8, 32) = 256 CTAs, 2/SM, one wave
    moe_mma_kernel<<<grid, 256, SMEM_TOTAL>>>(out);
}

// round 12
// speedup vs baseline: 1.1427x; 1.1217x over previous
#include <cuda_runtime.h>
#include <cuda_fp16.h>
#include <cstdint>

#define BATCH 4096
#define INF   1024
#define OUTF  1024
#define NL    16

#define BM 128
#define BN 128
#define BK 64                  // 4 i-values x 16 leaves per chunk
#define NIT (INF/4)            // 256 pw chunks
#define KCAT (INF*NL)

// smem layout (bytes)
#define X_OFF    0
#define X_BUF_B  1024          // 128 rows x 4 i x fp16
#define B_OFF    (3*X_BUF_B)   // 3072 (128B-aligned)
#define B_BUF_B  (BN*144)      // 18432 (144B pitch, LDSM conflict-free)
#define SMEM_TOTAL (B_OFF + 3*B_BUF_B)   // 58368 bytes

#define NPW_BLOCKS ((size_t)OUTF*KCAT/8/256)   // 8192
#define NX_BLOCKS  ((size_t)BATCH*INF/8/256)   // 2048

// device scratch (allocation-free)
__device__ __half g_gh[BATCH * NL];            // gating in fp16
__device__ __half g_xh[(size_t)BATCH * INF];   // x in fp16 (row-major)
__device__ __half g_pwh[(size_t)OUTF * KCAT];  // pw in fp16
__device__ __half g_pbh[OUTF * NL];            // pb in fp16

__device__ __forceinline__ uint32_t smem_u32_of(const void* p) {
    uint32_t a;
    asm("{ .reg .u64 t; cvta.to.shared.u64 t, %1; cvt.u32.u64 %0, t; }" : "=r"(a) : "l"(p));
    return a;
}
__device__ __forceinline__ uint32_t h2u(float lo, float hi) {
    __half2 h = __floats2half2_rn(lo, hi);
    return *(uint32_t*)&h;
}
__device__ __forceinline__ uint32_t hu(__half2 h) { return *(uint32_t*)&h; }
__device__ __forceinline__ void cp_async16(uint32_t sa, const void* ga) {
    asm volatile("cp.async.cg.shared.global [%0], [%1], 16;" :: "r"(sa), "l"(ga));
}
__device__ __forceinline__ void cp_async8(uint32_t sa, const void* ga) {
    asm volatile("cp.async.ca.shared.global [%0], [%1], 8;" :: "r"(sa), "l"(ga));
}
__device__ __forceinline__ void mma_f16(float* c, uint32_t a0, uint32_t a1,
                                        uint32_t a2, uint32_t a3,
                                        uint32_t b0, uint32_t b1) {
    asm volatile(
        "mma.sync.aligned.m16n8k16.row.col.f32.f16.f16.f32 "
        "{%0,%1,%2,%3}, {%4,%5,%6,%7}, {%8,%9}, {%0,%1,%2,%3};"
        : "+f"(c[0]), "+f"(c[1]), "+f"(c[2]), "+f"(c[3])
        : "r"(a0), "r"(a1), "r"(a2), "r"(a3), "r"(b0), "r"(b1));
}
__device__ __forceinline__ void ldsm_x4(uint32_t& r0, uint32_t& r1, uint32_t& r2, uint32_t& r3,
                                        uint32_t addr) {
    asm volatile("ldmatrix.sync.aligned.m8n8.x4.shared.b16 {%0,%1,%2,%3}, [%4];"
                 : "=r"(r0), "=r"(r1), "=r"(r2), "=r"(r3) : "r"(addr));
}

// ---------------------------------------------------------------------------
// prep: pw, x, pb -> fp16 (single launch, three grid sections)
// ---------------------------------------------------------------------------
__global__ __launch_bounds__(256)
void conv_kernel(const float* __restrict__ pw, const float* __restrict__ x,
                 const float* __restrict__ pb) {
    size_t bid = blockIdx.x;
    const float* src;
    __half* dst;
    size_t idx;
    if (bid < NPW_BLOCKS)            { src = pw; dst = g_pwh; idx = bid * 256 + threadIdx.x; }
    else if (bid < NPW_BLOCKS + NX_BLOCKS)
                                     { src = x;  dst = g_xh;  idx = (bid - NPW_BLOCKS) * 256 + threadIdx.x; }
    else                             { src = pb; dst = g_pbh; idx = (bid - NPW_BLOCKS - NX_BLOCKS) * 256 + threadIdx.x; }
    float4 v0 = ((const float4*)src)[idx * 2];
    float4 v1 = ((const float4*)src)[idx * 2 + 1];
    uint4 o;
    o.x = h2u(v0.x, v0.y); o.y = h2u(v0.z, v0.w);
    o.z = h2u(v1.x, v1.y); o.w = h2u(v1.z, v1.w);
    ((uint4*)dst)[idx] = o;
}

// ---------------------------------------------------------------------------
// gating: g = softmax(x @ gw + gb) -> fp16.
// 256 blocks, 2 rows/warp. gw filled via float4 LDG into pitch-17 smem
// (conflict-free scalar reads). x preloaded in 8-register chunks (no spill).
// ---------------------------------------------------------------------------
__global__ __launch_bounds__(256)
void gating_kernel(const float* __restrict__ x,
                   const float* __restrict__ gw,
                   const float* __restrict__ gb) {
    extern __shared__ float gw_s[];   // [1024][17]
    int tid = threadIdx.x, warp = tid >> 5, lane = tid & 31;

    // vectorized fill: 16 float4 per thread
    #pragma unroll
    for (int it = 0; it < 16; it++) {
        int idx = tid + it * 256;                 // 0..4095 float4s
        float4 v = ((const float4*)gw)[idx];
        int i = idx >> 2, l4 = (idx & 3) * 4;
        float* d = gw_s + i * 17 + l4;
        d[0] = v.x; d[1] = v.y; d[2] = v.z; d[3] = v.w;
    }
    __syncthreads();

    #pragma unroll 1
    for (int r = 0; r < 2; r++) {
        int row = blockIdx.x * 16 + warp * 2 + r;
        const float* xr = x + (size_t)row * INF;

        float acc[16];
        #pragma unroll
        for (int l = 0; l < 16; l++) acc[l] = 0.f;

        #pragma unroll 1
        for (int jb = 0; jb < 4; jb++) {
            // preload 8 x values (batched LDGs, bounded register use)
            float xv[8];
            #pragma unroll
            for (int u = 0; u < 8; u++) xv[u] = xr[lane + (jb * 8 + u) * 32];
            #pragma unroll
            for (int u = 0; u < 8; u++) {
                const float* gr = gw_s + (lane + (jb * 8 + u) * 32) * 17;
                #pragma unroll
                for (int l = 0; l < 16; l++) acc[l] = fmaf(xv[u], gr[l], acc[l]);
            }
        }
        #pragma unroll
        for (int o = 16; o > 0; o >>= 1)
            #pragma unroll
            for (int l = 0; l < 16; l++)
                acc[l] += __shfl_xor_sync(0xffffffffu, acc[l], o);

        if (lane < 16) {
            float v[16], m = -1e30f;
            #pragma unroll
            for (int l = 0; l < 16; l++) { v[l] = acc[l] + gb[l]; m = fmaxf(m, v[l]); }
            float s = 0.f;
            #pragma unroll
            for (int l = 0; l < 16; l++) { v[l] = __expf(v[l] - m); s += v[l]; }
            g_gh[row * NL + lane] = __float2half(v[lane] / s);
        }
    }
}

// ---------------------------------------------------------------------------
// main GEMM (R8-proven config): out = Y @ PW^T + g @ pb^T, mma.sync fp16
// m16n8k16, fp32 accum. A fragments generated in registers (g in regs,
// x via 1KB smem tile). B via cp.async + ldmatrix.x4, 3-buf distance-1.
// ---------------------------------------------------------------------------
__global__ __launch_bounds__(256, 2)
void moe_mma_kernel(float* __restrict__ out) {
    extern __shared__ char smc[];

    const int tid  = threadIdx.x;
    const int warp = tid >> 5, lane = tid & 31;
    const int m_blk = blockIdx.y * BM;
    const int n_blk = blockIdx.x * BN;
    const int warpM = warp & 1, warpN = warp >> 1;   // 2 x 4 warp grid, 64x32 each

    const int q = lane >> 2, cc = lane & 3;
    const int f8 = tid & 7, rb = tid >> 3;          // B loader roles

    // ---- g fragment pairs in registers (k-invariant) ----
    __half2 tg[4][4];
    #pragma unroll
    for (int mt = 0; mt < 4; mt++) {
        int r0 = m_blk + warpM * 64 + mt * 16 + q;
        int r1 = r0 + 8;
        tg[mt][0] = *(const __half2*)(g_gh + r0 * NL + 2 * cc);
        tg[mt][1] = *(const __half2*)(g_gh + r1 * NL + 2 * cc);
        tg[mt][2] = *(const __half2*)(g_gh + r0 * NL + 2 * cc + 8);
        tg[mt][3] = *(const __half2*)(g_gh + r1 * NL + 2 * cc + 8);
    }

    auto loadX = [&](int c, int buf) {
        if (tid < 128)
            cp_async8(smem_u32_of(smc + X_OFF + buf * X_BUF_B) + (uint32_t)tid * 8,
                      g_xh + (size_t)(m_blk + tid) * INF + c * 4);
    };
    auto loadB = [&](int c, int buf) {
        const __half* src = g_pwh + (size_t)n_blk * KCAT + (size_t)c * BK;
        uint32_t dst = smem_u32_of(smc + B_OFF + buf * B_BUF_B);
        #pragma unroll
        for (int qq = 0; qq < 4; qq++) {
            int row = rb + qq * 32;
            cp_async16(dst + (uint32_t)(row * 144 + f8 * 16),
                       src + (size_t)row * KCAT + f8 * 8);
        }
    };
    auto loadB_bias = [&](int buf) {
        int f2 = tid & 1, row = tid >> 1;     // 128 rows x 32B
        uint32_t dst = smem_u32_of(smc + B_OFF + buf * B_BUF_B);
        cp_async16(dst + (uint32_t)(row * 144 + f2 * 16),
                   g_pbh + (size_t)(n_blk + row) * NL + f2 * 8);
    };

    float acc[4][4][4];
    #pragma unroll
    for (int mt = 0; mt < 4; mt++)
        #pragma unroll
        for (int nt = 0; nt < 4; nt++)
            #pragma unroll
            for (int j = 0; j < 4; j++) acc[mt][nt][j] = 0.f;

    // B ldmatrix per-thread base (R6-proven mapping)
    const int lrow = warpN * 32 + (lane & 7) + ((lane >> 4) << 3);
    const uint32_t lcol16 = ((lane >> 3) & 1) << 4;
    const uint32_t bB0 = smem_u32_of(smc + B_OFF) + (uint32_t)lrow * 144 + lcol16;

    auto compute = [&](int buf) {
        const char* xt = smc + X_OFF + buf * X_BUF_B + (warpM * 64) * 8;
        __half2 xp0[4], xp1[4], xq0[4], xq1[4];
        #pragma unroll
        for (int mt = 0; mt < 4; mt++) {
            const __half2* p  = (const __half2*)(xt + (mt * 16 + q) * 8);
            const __half2* pq = (const __half2*)(xt + (mt * 16 + q + 8) * 8);
            xp0[mt] = p[0];  xp1[mt] = p[1];
            xq0[mt] = pq[0]; xq1[mt] = pq[1];
        }
        const uint32_t bb = bB0 + (uint32_t)buf * B_BUF_B;
        #pragma unroll
        for (int ks = 0; ks < 4; ks++) {
            uint32_t b[4][2];
            ldsm_x4(b[0][0], b[0][1], b[1][0], b[1][1], bb + ks * 32);
            ldsm_x4(b[2][0], b[2][1], b[3][0], b[3][1], bb + 16 * 144 + ks * 32);
            #pragma unroll
            for (int mt = 0; mt < 4; mt++) {
                __half2 xs0 = (ks == 0) ? __low2half2(xp0[mt]) :
                              (ks == 1) ? __high2half2(xp0[mt]) :
                              (ks == 2) ? __low2half2(xp1[mt]) : __high2half2(xp1[mt]);
                __half2 xs1 = (ks == 0) ? __low2half2(xq0[mt]) :
                              (ks == 1) ? __high2half2(xq0[mt]) :
                              (ks == 2) ? __low2half2(xq1[mt]) : __high2half2(xq1[mt]);
                uint32_t a0 = hu(__hmul2(xs0, tg[mt][0]));
                uint32_t a1 = hu(__hmul2(xs1, tg[mt][1]));
                uint32_t a2 = hu(__hmul2(xs0, tg[mt][2]));
                uint32_t a3 = hu(__hmul2(xs1, tg[mt][3]));
                #pragma unroll
                for (int nt = 0; nt < 4; nt++)
                    mma_f16(acc[mt][nt], a0, a1, a2, a3, b[nt][0], b[nt][1]);
            }
        }
    };
    auto compute_bias = [&](int buf) {
        const uint32_t bb = bB0 + (uint32_t)buf * B_BUF_B;
        uint32_t b[4][2];
        ldsm_x4(b[0][0], b[0][1], b[1][0], b[1][1], bb);
        ldsm_x4(b[2][0], b[2][1], b[3][0], b[3][1], bb + 16 * 144);
        #pragma unroll
        for (int mt = 0; mt < 4; mt++) {
            uint32_t a0 = hu(tg[mt][0]), a1 = hu(tg[mt][1]);
            uint32_t a2 = hu(tg[mt][2]), a3 = hu(tg[mt][3]);
            #pragma unroll
            for (int nt = 0; nt < 4; nt++)
                mma_f16(acc[mt][nt], a0, a1, a2, a3, b[nt][0], b[nt][1]);
        }
    };

    // ---- prologue: chunk 0 in flight ----
    loadX(0, 0);
    loadB(0, 0);
    asm volatile("cp.async.commit_group;" ::: "memory");

    // ---- main loop: distance-1, one barrier per chunk ----
    #pragma unroll 1
    for (int it = 0; it <= NIT; it++) {
        const int nc = it + 1;
        if (nc < NIT)        { loadX(nc, nc % 3); loadB(nc, nc % 3); }
        else if (nc == NIT)  { loadB_bias(nc % 3); }
        asm volatile("cp.async.commit_group;" ::: "memory");
        if (nc <= NIT) asm volatile("cp.async.wait_group 1;" ::: "memory");
        else           asm volatile("cp.async.wait_group 0;" ::: "memory");
        __syncthreads();
        if (it < NIT) compute(it % 3);
        else          compute_bias(it % 3);
    }

    // ---- epilogue: fragment store, 8B quad-coalesced ----
    #pragma unroll
    for (int mt = 0; mt < 4; mt++) {
        int m0 = m_blk + warpM * 64 + mt * 16 + (lane >> 2);
        #pragma unroll
        for (int nt = 0; nt < 4; nt++) {
            int n = n_blk + warpN * 32 + nt * 8 + 2 * (lane & 3);
            *(float2*)(out + (size_t)m0 * OUTF + n)       = make_float2(acc[mt][nt][0], acc[mt][nt][1]);
            *(float2*)(out + (size_t)(m0 + 8) * OUTF + n) = make_float2(acc[mt][nt][2], acc[mt][nt][3]);
        }
    }
}

// ---------------------------------------------------------------------------
extern "C" void kernel_launch(void* const* d_in, const int* in_sizes, int n_in,
                              void* d_out, int out_size) {
    const float* x  = (const float*)d_in[0];
    const float* gw = (const float*)d_in[1];
    const float* gb = (const float*)d_in[2];
    const float* pw = (const float*)d_in[3];
    const float* pb = (const float*)d_in[4];
    float* out = (float*)d_out;

    cudaFuncSetAttribute(gating_kernel, cudaFuncAttributeMaxDynamicSharedMemorySize,
                         INF * 17 * 4);
    cudaFuncSetAttribute(moe_mma_kernel, cudaFuncAttributeMaxDynamicSharedMemorySize,
                         SMEM_TOTAL);

    gating_kernel<<<BATCH / 16, 256, INF * 17 * 4>>>(x, gw, gb);
    conv_kernel<<<(unsigned)(NPW_BLOCKS + NX_BLOCKS + (OUTF * NL) / 8 / 256), 256>>>(pw, x, pb);

    dim3 grid(OUTF / BN, BATCH / BM);   // (8, 32) = 256 CTAs, 2/SM, one wave
    moe_mma_kernel<<<grid, 256, SMEM_TOTAL>>>(out);
}